// round 17
// baseline (speedup 1.0000x reference)
#include <cuda_runtime.h>

// Problem dims
#define NCC 4
#define BSZ 16
#define NTT 32
#define SSLICE (BSZ*64*64*12)   // 786432 floats per (BS,H,W,OC) slab

// Tile: 4 rows x 64 cols per CTA, 384 threads, 2 CTAs/SM.
#define SROW 66
#define SPX  (6*SROW)           // 396 staged pixels per channel

// Persistent device state
__device__ __align__(16) float g_slabs[5][SSLICE];
__device__ __align__(16) float g_class_c[NCC*SSLICE];
__device__ __align__(16) float g_genh[2][SSLICE];
__device__ __align__(16) float g_genc[SSLICE];

// Cached class-conv pre-activations: Z[pixel][48] = conv(class_view, Wx_g),
// stored in the reordered [third][gate][4] channel order.
__device__ __align__(16) float g_Z[4*SSLICE];

// Reordered weights: [k][ic][third][gate][4].
__device__ __align__(16) float g_wg[9*60*48];
__device__ __align__(16) float g_wc[9*36*48];

// Slab schedule.
__device__ int g_rslab[NTT*NCC];
__device__ int g_wslab[NTT];

__device__ __forceinline__ float hsig(float x) {
    return fminf(fmaxf(x + 3.0f, 0.0f), 6.0f) * (1.0f/6.0f);
}

typedef unsigned long long ull;

__device__ __forceinline__ ull pack2(float x) {
    ull r;
    unsigned int xi = __float_as_uint(x);
    asm("mov.b64 %0, {%1, %1};" : "=l"(r) : "r"(xi));
    return r;
}
__device__ __forceinline__ ull packpair(float a, float b) {
    ull r;
    asm("mov.b64 %0, {%1, %2};" : "=l"(r) : "f"(a), "f"(b));
    return r;
}
__device__ __forceinline__ void ffma2(ull& d, ull a, ull b) {
    asm("fma.rn.f32x2 %0, %1, %2, %0;" : "+l"(d) : "l"(a), "l"(b));
}
__device__ __forceinline__ float2 unpack2(ull v) {
    float2 r;
    asm("mov.b64 {%0, %1}, %2;" : "=f"(r.x), "=f"(r.y) : "l"(v));
    return r;
}

// --------------------------------------------------------------------------
// 12-channel conv tap, 16-oc third per thread, fully unrolled (immediate
// LDS offsets). xb channel-major with channel stride SPX; next row +SROW.
// --------------------------------------------------------------------------
__device__ __forceinline__ void conv12t(const float* __restrict__ sWk,
                                        const float* __restrict__ xb,
                                        ull* __restrict__ acc0,
                                        ull* __restrict__ acc1)
{
    const ulonglong2* wp = (const ulonglong2*)sWk;
    #pragma unroll
    for (int icc = 0; icc < 12; ++icc) {
        ull xp0 = pack2(xb[icc*SPX]);
        ull xp1 = pack2(xb[icc*SPX + SROW]);
        const ulonglong2* w = wp + icc*12;   // 48-float channel stride
        #pragma unroll
        for (int p = 0; p < 4; ++p) {
            ulonglong2 ww = w[p];
            ffma2(acc0[2*p],   xp0, ww.x);
            ffma2(acc0[2*p+1], xp0, ww.y);
            ffma2(acc1[2*p],   xp1, ww.x);
            ffma2(acc1[2*p+1], xp1, ww.y);
        }
    }
}

// --------------------------------------------------------------------------
__global__ void zero_kernel(float* __restrict__ out, const int* __restrict__ cids)
{
    const int tid    = blockIdx.x * blockDim.x + threadIdx.x;
    const int stride = gridDim.x * blockDim.x;
    for (int i = tid; i < 5*SSLICE; i += stride)
        (&g_slabs[0][0])[i] = 0.0f;
    for (int i = tid; i < 4*SSLICE; i += stride) {
        g_class_c[i] = 0.0f;
        g_Z[i]       = 0.0f;
    }
    for (int i = tid; i < SSLICE; i += stride) {
        g_genh[0][i] = 0.0f;
        g_genc[i]    = 0.0f;
        out[i]       = 0.0f;
    }
    if (tid == 0) {
        int slab[NCC] = {0, 1, 2, 3};
        int spare = 4;
        for (int t = 0; t < NTT; ++t) {
            int cid = cids[t];
            #pragma unroll
            for (int c = 0; c < NCC; ++c) g_rslab[t*4 + c] = slab[c];
            g_wslab[t] = spare;
            int old = slab[cid];
            slab[cid] = spare;
            spare = old;
        }
    }
}

// --------------------------------------------------------------------------
// One-time weight reorder into [k][ic][third][gate][4] layout.
// --------------------------------------------------------------------------
__global__ void reorder_kernel(const float* __restrict__ Wxg, const float* __restrict__ Whg,
                               const float* __restrict__ Wxc, const float* __restrict__ Whc)
{
    const int tid    = blockIdx.x * blockDim.x + threadIdx.x;
    const int stride = gridDim.x * blockDim.x;
    const float4* wx4 = (const float4*)Wxg;
    const float4* wh4 = (const float4*)Whg;
    for (int e = tid; e < 9*60*12; e += stride) {
        int th   = e % 3;
        int gate = (e/3) & 3;
        int ic   = (e/12) % 60;
        int k    = e / 720;
        float4 v = (ic < 48) ? wx4[(k*48 + ic)*12 + gate*3 + th]
                             : wh4[(k*12 + (ic - 48))*12 + gate*3 + th];
        ((float4*)g_wg)[((k*60 + ic)*3 + th)*4 + gate] = v;
    }
    const float4* cx4 = (const float4*)Wxc;
    const float4* ch4 = (const float4*)Whc;
    for (int e = tid; e < 9*36*12; e += stride) {
        int th   = e % 3;
        int gate = (e/3) & 3;
        int ic   = (e/12) % 36;
        int k    = e / 432;
        float4 v = (ic < 24) ? cx4[(k*24 + ic)*12 + gate*3 + th]
                             : ch4[(k*12 + (ic - 24))*12 + gate*3 + th];
        ((float4*)g_wc)[((k*36 + ic)*3 + th)*4 + gate] = v;
    }
}

// ==========================================================================
// Delta kernel: Z += conv(new_slab - old_slab, Wx-chunk) for the 4 batches
// whose class view changed at tprev. Grid (16,16): x = row-tile (4 rows),
// y -> (batch quarter = by&3, chunk = by>>2). 384 threads, 2 CTAs/SM.
// ==========================================================================
#define D_SW   (9*12*48)            // 5184 floats
#define D_SIN  (12*SPX)             // 4752 floats
#define D_SMEM_BYTES ((D_SW + D_SIN)*4)

__global__ __launch_bounds__(384, 2)
void delta_kernel(const int* __restrict__ cids, int tprev)
{
    extern __shared__ float smem[];
    float* sW  = smem;
    float* sIn = smem + D_SW;

    const int tid = threadIdx.x;
    const int tx  = tid & 63;
    const int rg  = (tid >> 6) & 1;
    const int th  = tid >> 7;          // 0..2
    const int cid = __ldg(cids + tprev);
    const int batch = cid*4 + (blockIdx.y & 3);
    const int chunk = blockIdx.y >> 2;
    const int y0  = blockIdx.x * 4;

    const float* news = g_slabs[g_wslab[tprev]];
    const float* olds = g_slabs[g_rslab[tprev*4 + cid]];

    for (int k = 0; k < 9; ++k) {
        const float4* s4 = (const float4*)(g_wg + (k*60 + chunk*12)*48);
        float4*       d4 = (float4*)(sW + k*576);
        if (tid < 144) d4[tid] = s4[tid];
    }

    #pragma unroll 1
    for (int e = tid; e < 3*SPX; e += 384) {
        int px = e / 3;
        int q  = e - px*3;
        int yy = px / SROW;
        int xx = px - yy*SROW;
        int gy = y0 + yy - 1;
        int gx = xx - 1;
        float4 v = make_float4(0.f, 0.f, 0.f, 0.f);
        if ((unsigned)gy < 64u && (unsigned)gx < 64u) {
            size_t off = (size_t)((batch & 3)*4096 + gy*64 + gx)*48 + chunk*12 + q*4;
            float4 a = *(const float4*)(news + off);
            float4 o = *(const float4*)(olds + off);
            v = make_float4(a.x - o.x, a.y - o.y, a.z - o.z, a.w - o.w);
        }
        sIn[(q*4 + 0)*SPX + px] = v.x;
        sIn[(q*4 + 1)*SPX + px] = v.y;
        sIn[(q*4 + 2)*SPX + px] = v.z;
        sIn[(q*4 + 3)*SPX + px] = v.w;
    }
    __syncthreads();

    ull acc0[8], acc1[8];
    #pragma unroll
    for (int p = 0; p < 8; ++p) { acc0[p] = 0ull; acc1[p] = 0ull; }

    #pragma unroll 1
    for (int k = 0; k < 9; ++k) {
        const int ky = k / 3;
        const int kx = k - ky*3;
        conv12t(sW + k*576 + th*16,
                sIn + (rg*2 + ky)*SROW + tx + kx,
                acc0, acc1);
    }

    #pragma unroll
    for (int r = 0; r < 2; ++r) {
        ull* accr = r ? acc1 : acc0;
        const int gy   = y0 + rg*2 + r;
        const int pidx = (batch*64 + gy)*64 + tx;
        float4* zp = (float4*)(g_Z + (size_t)pidx*48 + th*16);
        #pragma unroll
        for (int p2 = 0; p2 < 4; ++p2) {
            float2 lo = unpack2(accr[2*p2]);
            float2 hi = unpack2(accr[2*p2+1]);
            atomicAdd(zp + p2, make_float4(lo.x, lo.y, hi.x, hi.y));
        }
    }
}

// ==========================================================================
// General cell (incremental): gates = Z + conv(genh, Wh) + bias.
// Grid (16,16), 384 threads, 2 CTAs/SM.
// ==========================================================================
#define G_SW   (9*12*48)
#define G_SIN  (12*SPX)
#define G_SMEM_BYTES ((G_SW + G_SIN + 48)*4)

__global__ __launch_bounds__(384, 2)
void gen_cell_kernel(const float* __restrict__ bias, int t, int par)
{
    extern __shared__ float smem[];
    float* sW  = smem;
    float* sIn = smem + G_SW;
    float* sB  = smem + G_SW + G_SIN;

    const int tid = threadIdx.x;
    const int tx  = tid & 63;
    const int rg  = (tid >> 6) & 1;
    const int th  = tid >> 7;
    const int b   = blockIdx.y;
    const int y0  = blockIdx.x * 4;

    const float* genh_in  = g_genh[par];
    float*       genh_out = g_genh[par ^ 1];

    for (int k = 0; k < 9; ++k) {
        const float4* s4 = (const float4*)(g_wg + (k*60 + 48)*48);
        float4*       d4 = (float4*)(sW + k*576);
        if (tid < 144) d4[tid] = s4[tid];
    }
    if (tid < 12) ((float4*)sB)[tid] = ((const float4*)bias)[tid];

    #pragma unroll 1
    for (int e = tid; e < 3*SPX; e += 384) {
        int px = e / 3;
        int q  = e - px*3;
        int yy = px / SROW;
        int xx = px - yy*SROW;
        int gy = y0 + yy - 1;
        int gx = xx - 1;
        float4 v = make_float4(0.f, 0.f, 0.f, 0.f);
        if ((unsigned)gy < 64u && (unsigned)gx < 64u) {
            int pidx = (b*64 + gy)*64 + gx;
            v = *(const float4*)(genh_in + (size_t)pidx*12 + q*4);
        }
        sIn[(q*4 + 0)*SPX + px] = v.x;
        sIn[(q*4 + 1)*SPX + px] = v.y;
        sIn[(q*4 + 2)*SPX + px] = v.z;
        sIn[(q*4 + 3)*SPX + px] = v.w;
    }

    // Init accumulators from cached Z
    ull acc0[8], acc1[8];
    {
        const int pidx0 = (b*64 + y0 + rg*2)*64 + tx;
        const float4* z0 = (const float4*)(g_Z + (size_t)pidx0*48 + th*16);
        const float4* z1 = (const float4*)(g_Z + (size_t)(pidx0 + 64)*48 + th*16);
        #pragma unroll
        for (int p2 = 0; p2 < 4; ++p2) {
            float4 v0 = z0[p2];
            float4 v1 = z1[p2];
            acc0[2*p2]   = packpair(v0.x, v0.y);
            acc0[2*p2+1] = packpair(v0.z, v0.w);
            acc1[2*p2]   = packpair(v1.x, v1.y);
            acc1[2*p2+1] = packpair(v1.z, v1.w);
        }
    }
    __syncthreads();

    #pragma unroll 1
    for (int k = 0; k < 9; ++k) {
        const int ky = k / 3;
        const int kx = k - ky*3;
        conv12t(sW + k*576 + th*16,
                sIn + (rg*2 + ky)*SROW + tx + kx,
                acc0, acc1);
    }

    #pragma unroll
    for (int r = 0; r < 2; ++r) {
        ull* accr = r ? acc1 : acc0;
        float z[16];
        #pragma unroll
        for (int p = 0; p < 8; ++p) {
            float2 v = unpack2(accr[p]);
            z[2*p] = v.x; z[2*p+1] = v.y;
        }
        const int gy  = y0 + rg*2 + r;
        const int idx = ((b*64 + gy)*64 + tx)*12 + th*4;
        float4 c4 = *(const float4*)(g_genc + idx);
        float4 h4;
        float* cf = (float*)&c4;
        float* hf = (float*)&h4;
        #pragma unroll
        for (int j = 0; j < 4; ++j) {
            float zi = z[j]      + sB[th*4 + j];
            float zf = z[4 + j]  + sB[12 + th*4 + j];
            float zg = z[8 + j]  + sB[24 + th*4 + j];
            float zo = z[12 + j] + sB[36 + th*4 + j];
            float fi = hsig(zi), ff = hsig(zf), fo = hsig(zo);
            float cn = ff * cf[j] + fi * tanhf(zg);
            cf[j] = cn;
            hf[j] = fo * tanhf(cn);
        }
        *(float4*)(g_genc + idx)   = c4;
        *(float4*)(genh_out + idx) = h4;
    }
}

// ==========================================================================
// Class cell: 3 chunks of 12 (frame, fresh gen_h, class_h[cid]).
// Grid (16,16), 384 threads, 2 CTAs/SM. Writes h_new into slab wslab[t];
// accumulates out.
// ==========================================================================
#define B_SW   (9*36*48)
#define B_SIN  (12*SPX)
#define B_SMEM_BYTES ((B_SW + B_SIN + 48)*4)

__device__ __forceinline__ float4 ldsrc_cls(const float* __restrict__ frame,
                                            const float* __restrict__ genh_new,
                                            const float* __restrict__ chh,
                                            int ch, int pidx, int q, bool ok)
{
    if (!ok) return make_float4(0.f, 0.f, 0.f, 0.f);
    const float* src = (ch == 0) ? frame + (size_t)(pidx & 4095)*12
                     : (ch == 1) ? genh_new + (size_t)pidx*12
                                 : chh + (size_t)pidx*12;
    return *(const float4*)(src + q*4);
}

__global__ __launch_bounds__(384, 2)
void cls_cell_kernel(const float* __restrict__ x, const int* __restrict__ class_ids,
                     const float* __restrict__ bias, int t, int par,
                     float* __restrict__ out)
{
    extern __shared__ float smem[];
    float* sW  = smem;
    float* sIn = smem + B_SW;
    float* sB  = smem + B_SW + B_SIN;

    const int tid = threadIdx.x;
    const int tx  = tid & 63;
    const int rg  = (tid >> 6) & 1;
    const int th  = tid >> 7;
    const int b   = blockIdx.y;
    const int y0  = blockIdx.x * 4;
    const int cid = __ldg(class_ids + t);

    const float* genh_new = g_genh[par ^ 1];
    const float* chh      = g_slabs[g_rslab[t*4 + cid]];
    float*       hnew     = g_slabs[g_wslab[t]];
    const float* frame    = x + (size_t)(b*NTT + t)*4096*12;

    {
        const float4* s4 = (const float4*)g_wc;
        float4*       d4 = (float4*)sW;
        #pragma unroll
        for (int i = 0; i < 11; ++i) {
            int e = tid + i*384;
            if (e < 3888) d4[e] = s4[e];
        }
    }
    if (tid < 12) ((float4*)sB)[tid] = ((const float4*)bias)[tid];

    // Staging coordinates: 4 slots/thread (ceil(1188/384)=4), invariant.
    int ppx[4], pq[4], ppidx[4];
    bool pok[4], pinr[4];
    #pragma unroll
    for (int i = 0; i < 4; ++i) {
        int e  = tid + i*384;
        bool inr = e < 3*SPX;
        int px = e/3, q = e - px*3;
        int yy = px/SROW, xx = px - yy*SROW;
        int gy = y0 + yy - 1, gx = xx - 1;
        bool inb = inr && (unsigned)gy < 64u && (unsigned)gx < 64u;
        ppx[i] = px; pq[i] = q;
        ppidx[i] = inb ? ((b*64 + gy)*64 + gx) : 0;
        pok[i] = inb; pinr[i] = inr;
    }

    ull acc0[8], acc1[8];
    #pragma unroll
    for (int p = 0; p < 8; ++p) { acc0[p] = 0ull; acc1[p] = 0ull; }

    float4 pf[4];
    #pragma unroll
    for (int i = 0; i < 4; ++i)
        pf[i] = ldsrc_cls(frame, genh_new, chh, 0, ppidx[i], pq[i], pok[i]);

    #pragma unroll 1
    for (int ch = 0; ch < 3; ++ch) {
        __syncthreads();
        #pragma unroll
        for (int i = 0; i < 4; ++i) {
            if (pinr[i]) {
                int base = pq[i]*4*SPX + ppx[i];
                sIn[base]          = pf[i].x;
                sIn[base +   SPX]  = pf[i].y;
                sIn[base + 2*SPX]  = pf[i].z;
                sIn[base + 3*SPX]  = pf[i].w;
            }
        }
        __syncthreads();
        if (ch < 2) {
            #pragma unroll
            for (int i = 0; i < 4; ++i)
                pf[i] = ldsrc_cls(frame, genh_new, chh, ch + 1, ppidx[i], pq[i], pok[i]);
        }

        #pragma unroll 1
        for (int k = 0; k < 9; ++k) {
            const int ky = k / 3;
            const int kx = k - ky*3;
            conv12t(sW + ((k*36 + ch*12)*3 + th)*16,
                    sIn + (rg*2 + ky)*SROW + tx + kx,
                    acc0, acc1);
        }
    }

    float* chc = g_class_c + (size_t)cid * SSLICE;

    #pragma unroll
    for (int r = 0; r < 2; ++r) {
        ull* accr = r ? acc1 : acc0;
        float z[16];
        #pragma unroll
        for (int p = 0; p < 8; ++p) {
            float2 v = unpack2(accr[p]);
            z[2*p] = v.x; z[2*p+1] = v.y;
        }
        const int gy  = y0 + rg*2 + r;
        const int idx = ((b*64 + gy)*64 + tx)*12 + th*4;
        float4 c4 = *(const float4*)(chc + idx);
        float4 o4 = *(const float4*)(out + idx);
        float4 h4;
        float* cf = (float*)&c4;
        float* hf = (float*)&h4;
        float* of = (float*)&o4;
        #pragma unroll
        for (int j = 0; j < 4; ++j) {
            float zi = z[j]      + sB[th*4 + j];
            float zf = z[4 + j]  + sB[12 + th*4 + j];
            float zg = z[8 + j]  + sB[24 + th*4 + j];
            float zo = z[12 + j] + sB[36 + th*4 + j];
            float fi = hsig(zi), ff = hsig(zf), fo = hsig(zo);
            float cn = ff * cf[j] + fi * tanhf(zg);
            float hn = fo * tanhf(cn);
            cf[j] = cn;
            hf[j] = hn;
            of[j] += hn;
        }
        *(float4*)(chc + idx)  = c4;
        *(float4*)(hnew + idx) = h4;
        *(float4*)(out + idx)  = o4;
    }
}

// --------------------------------------------------------------------------
extern "C" void kernel_launch(void* const* d_in, const int* in_sizes, int n_in,
                              void* d_out, int out_size)
{
    const float* x    = (const float*)d_in[0];
    const int*   cids = (const int*)d_in[1];
    const float* Wxg  = (const float*)d_in[2];
    const float* Whg  = (const float*)d_in[3];
    const float* bg   = (const float*)d_in[4];
    const float* Wxc  = (const float*)d_in[5];
    const float* Whc  = (const float*)d_in[6];
    const float* bc   = (const float*)d_in[7];
    float* out = (float*)d_out;

    cudaFuncSetAttribute(delta_kernel,    cudaFuncAttributeMaxDynamicSharedMemorySize, D_SMEM_BYTES);
    cudaFuncSetAttribute(gen_cell_kernel, cudaFuncAttributeMaxDynamicSharedMemorySize, G_SMEM_BYTES);
    cudaFuncSetAttribute(cls_cell_kernel, cudaFuncAttributeMaxDynamicSharedMemorySize, B_SMEM_BYTES);

    zero_kernel<<<1024, 256>>>(out, cids);
    reorder_kernel<<<64, 256>>>(Wxg, Whg, Wxc, Whc);

    for (int t = 0; t < NTT; ++t) {
        const int par = t & 1;
        if (t > 0)
            delta_kernel<<<dim3(16, 16), 384, D_SMEM_BYTES>>>(cids, t - 1);
        gen_cell_kernel<<<dim3(16, 16), 384, G_SMEM_BYTES>>>(bg, t, par);
        cls_cell_kernel<<<dim3(16, 16), 384, B_SMEM_BYTES>>>(x, cids, bc, t, par, out);
    }
}